// round 8
// baseline (speedup 1.0000x reference)
#include <cuda_runtime.h>
#include <cuda_bf16.h>
#include <cstdint>

// Problem constants (fixed by the dataset)
#define B_SZ   1024
#define NIN    2048
#define NOUT   2048
#define NC     10
#define TSTEPS 10

#define DECAY  0.2f
#define THRESH 0.5f
#define TD     0.1f   // THRESH * DECAY

// Scratch: h = x @ W_enc^T  (8 MB) and per-row loss partials.
__device__ float g_h[B_SZ * NOUT];
__device__ float g_lossPartial[B_SZ];

// ---------------------------------------------------------------------------
// Packed fp32x2 helpers (Blackwell: fma.rn.f32x2 — 2 IEEE fp32 FMAs per issue)
// ---------------------------------------------------------------------------
__device__ __forceinline__ unsigned long long pack2(float lo, float hi) {
    unsigned long long d;
    asm("mov.b64 %0, {%1, %2};" : "=l"(d)
        : "r"(__float_as_int(lo)), "r"(__float_as_int(hi)));
    return d;
}
__device__ __forceinline__ void unpack2(unsigned long long v, float& lo, float& hi) {
    int a, b;
    asm("mov.b64 {%0, %1}, %2;" : "=r"(a), "=r"(b) : "l"(v));
    lo = __int_as_float(a); hi = __int_as_float(b);
}
__device__ __forceinline__ unsigned long long ffma2(unsigned long long a,
                                                    unsigned long long b,
                                                    unsigned long long c) {
    unsigned long long d;
    asm("fma.rn.f32x2 %0, %1, %2, %3;" : "=l"(d) : "l"(a), "l"(b), "l"(c));
    return d;
}
__device__ __forceinline__ unsigned long long fadd2(unsigned long long a,
                                                    unsigned long long b) {
    unsigned long long d;
    asm("add.rn.f32x2 %0, %1, %2;" : "=l"(d) : "l"(a), "l"(b));
    return d;
}

// ---------------------------------------------------------------------------
// Kernel 1: fp32 GEMM  C[M,N] = A[M,K] * B[N,K]^T  via packed f32x2 FMA.
// 128x128 CTA tile, BK=16, 256 threads, 8x8 per-thread microtile.
// Warp footprint remapped to 4 tx x 8 ty so per-warp LDS spans are small:
//   B fragment LDS.128 -> 128 B span, 4-way broadcast, 1 wavefront
//   A fragment LDS.128 -> 256 B span, 2 wavefronts
// (6 wf/warp/k vs 10 before). Arithmetic per output element unchanged.
// ---------------------------------------------------------------------------
#define BM 128
#define BN 128
#define BK 16

__global__ __launch_bounds__(256, 1)
void gemm_f32x2_nt(const float* __restrict__ A, const float* __restrict__ Bm,
                   float* __restrict__ C)
{
    __shared__ __align__(16) float As[2][BK][BM + 4];
    __shared__ __align__(16) float Bs[2][BK][BN + 4];

    const int tid = threadIdx.x;
    const int w = tid >> 5, l = tid & 31;
    // Warp-local remap: 4 tx values x 8 ty values per warp.
    const int tx = (l & 3) + ((w & 3) << 2);     // 0..15 -> N microtile (8 cols)
    const int ty = (l >> 2) + ((w >> 2) << 3);   // 0..15 -> M microtile (8 rows)
    const int bm = blockIdx.y * BM;
    const int bn = blockIdx.x * BN;

    const float* Ab = A + (size_t)bm * NIN;
    const float* Bb = Bm + (size_t)bn * NIN;

    // Global->SMEM mapping: each 128x16 tile = 2 float4 per thread.
    const int lrow = tid >> 2;            // 0..63
    const int lcol = (tid & 3) << 2;      // 0,4,8,12

    unsigned long long acc[4][8];         // [row-pair][col]
#pragma unroll
    for (int i = 0; i < 4; i++)
#pragma unroll
        for (int j = 0; j < 8; j++) acc[i][j] = 0ull;

    // Prologue: load K-tile 0 into buffer 0.
    float4 pa0 = *(const float4*)(Ab + (size_t)lrow * NIN + lcol);
    float4 pa1 = *(const float4*)(Ab + (size_t)(lrow + 64) * NIN + lcol);
    float4 pb0 = *(const float4*)(Bb + (size_t)lrow * NIN + lcol);
    float4 pb1 = *(const float4*)(Bb + (size_t)(lrow + 64) * NIN + lcol);
#pragma unroll
    for (int v = 0; v < 4; v++) {
        As[0][lcol + v][lrow]      = (&pa0.x)[v];
        As[0][lcol + v][lrow + 64] = (&pa1.x)[v];
        Bs[0][lcol + v][lrow]      = (&pb0.x)[v];
        Bs[0][lcol + v][lrow + 64] = (&pb1.x)[v];
    }
    __syncthreads();

    const int NT = NIN / BK;   // 128
    for (int t = 0; t < NT; t++) {
        const int p = t & 1;
        // Prefetch next K-tile into registers (overlaps with compute).
        if (t + 1 < NT) {
            const int ko = (t + 1) * BK;
            pa0 = *(const float4*)(Ab + (size_t)lrow * NIN + ko + lcol);
            pa1 = *(const float4*)(Ab + (size_t)(lrow + 64) * NIN + ko + lcol);
            pb0 = *(const float4*)(Bb + (size_t)lrow * NIN + ko + lcol);
            pb1 = *(const float4*)(Bb + (size_t)(lrow + 64) * NIN + ko + lcol);
        }

#pragma unroll
        for (int k = 0; k < BK; k++) {
            // A: two float4 = four packed row-pair u64 (pure reinterpret).
            ulonglong2 a01 = *(const ulonglong2*)&As[p][k][ty * 8];
            ulonglong2 a23 = *(const ulonglong2*)&As[p][k][ty * 8 + 4];
            float4 vb0 = *(const float4*)&Bs[p][k][tx * 8];
            float4 vb1 = *(const float4*)&Bs[p][k][tx * 8 + 4];

            unsigned long long a2[4];
            a2[0] = a01.x; a2[1] = a01.y; a2[2] = a23.x; a2[3] = a23.y;
            unsigned long long b2[8];
            b2[0] = pack2(vb0.x, vb0.x); b2[1] = pack2(vb0.y, vb0.y);
            b2[2] = pack2(vb0.z, vb0.z); b2[3] = pack2(vb0.w, vb0.w);
            b2[4] = pack2(vb1.x, vb1.x); b2[5] = pack2(vb1.y, vb1.y);
            b2[6] = pack2(vb1.z, vb1.z); b2[7] = pack2(vb1.w, vb1.w);
#pragma unroll
            for (int i = 0; i < 4; i++)
#pragma unroll
                for (int j = 0; j < 8; j++)
                    acc[i][j] = ffma2(a2[i], b2[j], acc[i][j]);
        }

        if (t + 1 < NT) {
            const int q = p ^ 1;
#pragma unroll
            for (int v = 0; v < 4; v++) {
                As[q][lcol + v][lrow]      = (&pa0.x)[v];
                As[q][lcol + v][lrow + 64] = (&pa1.x)[v];
                Bs[q][lcol + v][lrow]      = (&pb0.x)[v];
                Bs[q][lcol + v][lrow + 64] = (&pb1.x)[v];
            }
            __syncthreads();
        }
    }

    // Epilogue: unpack row-pairs; each row stores 8 floats as 2x float4.
#pragma unroll
    for (int i = 0; i < 4; i++) {
        float r0[8], r1[8];
#pragma unroll
        for (int j = 0; j < 8; j++) unpack2(acc[i][j], r0[j], r1[j]);
        const size_t rowA = (size_t)(bm + ty * 8 + 2 * i) * NOUT + bn + tx * 8;
        *(float4*)&C[rowA]            = *(float4*)&r0[0];
        *(float4*)&C[rowA + 4]        = *(float4*)&r0[4];
        *(float4*)&C[rowA + NOUT]     = *(float4*)&r1[0];
        *(float4*)&C[rowA + NOUT + 4] = *(float4*)&r1[4];
    }
}

// ---------------------------------------------------------------------------
// Kernel 2: full SNN recurrence. One CTA per batch row; 256 threads.
// Each thread owns 8 neurons (j = tid + 256*i). W_dec held in REGISTERS
// (40 packed f32x2 per thread). Decoder partials via f32x2 FMA.
// Reduction: 3 butterfly rounds (32 -> 4 lanes), lanes 0..3 spill to SMEM,
// threads 0..9 finish 32 partials serially. (Fewer SHFL slots than a full
// 5-round tree; only perturbs the loss path by ~1e-7, not the spikes.)
// ---------------------------------------------------------------------------
__global__ __launch_bounds__(256)
void snn_steps(const float* __restrict__ h, const float* __restrict__ Wdec,
               const float* __restrict__ yoh, float* __restrict__ out,
               float* __restrict__ lossPartial)
{
    __shared__ float red[32 * NC + NC];   // 32 partials x 10 classes + scratch

    const int b = blockIdx.x;
    const int tid = threadIdx.x;
    const int warp = tid >> 5, lane = tid & 31;

    // Load decoder weights into registers, packed by class pair:
    // w2[i][c] = { Wdec[2c][j], Wdec[2c+1][j] },  j = tid + 256*i
    unsigned long long w2[8][5];
#pragma unroll
    for (int i = 0; i < 8; i++) {
        const int j = tid + 256 * i;
#pragma unroll
        for (int c = 0; c < 5; c++)
            w2[i][c] = pack2(Wdec[(2 * c) * NOUT + j],
                             Wdec[(2 * c + 1) * NOUT + j]);
    }

    float hreg[8], mem[8], spk[8];
#pragma unroll
    for (int i = 0; i < 8; i++) {
        hreg[i] = h[(size_t)b * NOUT + tid + 256 * i];
        mem[i] = 0.0f; spk[i] = 0.0f;
    }

    float ym = 0.0f, ys = 0.0f, yo = 0.0f, lossc = 0.0f;
    if (tid < NC) yo = yoh[b * NC + tid];
    __syncthreads();

    for (int t = 0; t < TSTEPS; t++) {
        unsigned long long acc2[5];
#pragma unroll
        for (int c = 0; c < 5; c++) acc2[c] = 0ull;

#pragma unroll
        for (int i = 0; i < 8; i++) {
            mem[i] = mem[i] * DECAY + hreg[i] - spk[i] * TD;
            spk[i] = (mem[i] > THRESH) ? 1.0f : 0.0f;
            const int j = tid + 256 * i;
            out[(size_t)t * (B_SZ * NOUT) + (size_t)b * NOUT + j] = spk[i];
            const unsigned long long s2 = pack2(spk[i], spk[i]);
#pragma unroll
            for (int c = 0; c < 5; c++)
                acc2[c] = ffma2(s2, w2[i][c], acc2[c]);
        }

        // 3 butterfly rounds: lanes 0..3 end up holding partial sums.
#pragma unroll
        for (int c = 0; c < 5; c++) {
#pragma unroll
            for (int o = 16; o >= 4; o >>= 1) {
                unsigned long long other =
                    __shfl_down_sync(0xffffffffu, acc2[c], o);
                acc2[c] = fadd2(acc2[c], other);
            }
        }
        if (lane < 4) {
            const int part = warp * 4 + lane;   // 0..31
#pragma unroll
            for (int c = 0; c < 5; c++) {
                float lo, hi;
                unpack2(acc2[c], lo, hi);
                red[(2 * c) * 32 + part]     = lo;
                red[(2 * c + 1) * 32 + part] = hi;
            }
        }
        __syncthreads();

        if (tid < NC) {
            float tot = 0.0f;
#pragma unroll
            for (int p = 0; p < 32; p++) tot += red[tid * 32 + p];
            ym = ym * DECAY + tot - ys * TD;
            ys = (ym > THRESH) ? 1.0f : 0.0f;
            const float d = ys - yo;
            lossc = fmaf(d, d, lossc);
        }
        __syncthreads();   // protect red before next step reuses it
    }

    if (tid < NC) red[32 * NC + tid] = lossc;
    __syncthreads();
    if (tid == 0) {
        float s = 0.0f;
#pragma unroll
        for (int c = 0; c < NC; c++) s += red[32 * NC + c];
        lossPartial[b] = s;
    }
}

// ---------------------------------------------------------------------------
// Kernel 3: reduce per-row loss partials -> out[out_size-1]
// ---------------------------------------------------------------------------
__global__ void loss_reduce(const float* __restrict__ lp, float* __restrict__ out,
                            int out_size)
{
    __shared__ float s[256];
    float v = 0.0f;
    for (int i = threadIdx.x; i < B_SZ; i += 256) v += lp[i];
    s[threadIdx.x] = v;
    __syncthreads();
    for (int o = 128; o > 0; o >>= 1) {
        if (threadIdx.x < o) s[threadIdx.x] += s[threadIdx.x + o];
        __syncthreads();
    }
    if (threadIdx.x == 0)
        out[out_size - 1] = s[0] / (float)(B_SZ * NC);  // mean over [B, NC], summed over T
}

// ---------------------------------------------------------------------------
extern "C" void kernel_launch(void* const* d_in, const int* in_sizes, int n_in,
                              void* d_out, int out_size)
{
    const float* x     = (const float*)d_in[0];   // [1024, 2048]
    const float* W_enc = (const float*)d_in[1];   // [2048, 2048]
    const float* W_dec = (const float*)d_in[2];   // [10, 2048]
    const float* y_oh  = (const float*)d_in[3];   // [1024, 10]
    float* out = (float*)d_out;

    float* h;
    cudaGetSymbolAddress((void**)&h, g_h);
    float* lp;
    cudaGetSymbolAddress((void**)&lp, g_lossPartial);

    // GEMM: h = x @ W_enc^T   (grid = 16 x 8 = 128 CTAs)
    dim3 ggrid(NOUT / BN, B_SZ / BM);
    gemm_f32x2_nt<<<ggrid, 256>>>(x, W_enc, h);

    // Recurrence
    snn_steps<<<B_SZ, 256>>>(h, W_dec, y_oh, out, lp);

    // Final loss scalar
    loss_reduce<<<1, 256>>>(lp, out, out_size);
}

// round 12
// speedup vs baseline: 1.1695x; 1.1695x over previous
#include <cuda_runtime.h>
#include <cuda_bf16.h>
#include <cstdint>

// Problem constants (fixed by the dataset)
#define B_SZ   1024
#define NIN    2048
#define NOUT   2048
#define NC     10
#define TSTEPS 10

#define DECAY  0.2f
#define THRESH 0.5f
#define TD     0.1f   // THRESH * DECAY
#define RISK_DELTA 1e-3f

// Scratch
__device__ float g_h[B_SZ * NOUT];
__device__ float g_lossPartial[B_SZ];
// 2-way bf16 splits of x and W_enc (16B-aligned for cp.async)
__device__ __align__(16) __nv_bfloat16 g_Asp[2 * B_SZ * NIN];   // 8 MB
__device__ __align__(16) __nv_bfloat16 g_Bsp[2 * NOUT * NIN];   // 16 MB

// ---------------------------------------------------------------------------
// Packed fp32x2 helpers (for the snn kernel)
// ---------------------------------------------------------------------------
__device__ __forceinline__ unsigned long long pack2(float lo, float hi) {
    unsigned long long d;
    asm("mov.b64 %0, {%1, %2};" : "=l"(d)
        : "r"(__float_as_int(lo)), "r"(__float_as_int(hi)));
    return d;
}
__device__ __forceinline__ void unpack2(unsigned long long v, float& lo, float& hi) {
    int a, b;
    asm("mov.b64 {%0, %1}, %2;" : "=r"(a), "=r"(b) : "l"(v));
    lo = __int_as_float(a); hi = __int_as_float(b);
}
__device__ __forceinline__ unsigned long long ffma2(unsigned long long a,
                                                    unsigned long long b,
                                                    unsigned long long c) {
    unsigned long long d;
    asm("fma.rn.f32x2 %0, %1, %2, %3;" : "=l"(d) : "l"(a), "l"(b), "l"(c));
    return d;
}
__device__ __forceinline__ unsigned long long fadd2(unsigned long long a,
                                                    unsigned long long b) {
    unsigned long long d;
    asm("add.rn.f32x2 %0, %1, %2;" : "=l"(d) : "l"(a), "l"(b));
    return d;
}

// ---------------------------------------------------------------------------
// sm_80-era PTX helpers (valid on compute_103 base target)
// ---------------------------------------------------------------------------
__device__ __forceinline__ uint32_t smem_u32(const void* p) {
    uint32_t a;
    asm("{ .reg .u64 t; cvta.to.shared.u64 t, %1; cvt.u32.u64 %0, t; }"
        : "=r"(a) : "l"(p));
    return a;
}
__device__ __forceinline__ void cp16(uint32_t saddr, const void* gaddr) {
    asm volatile("cp.async.cg.shared.global [%0], [%1], 16;"
                 :: "r"(saddr), "l"(gaddr) : "memory");
}
__device__ __forceinline__ void cp_commit() {
    asm volatile("cp.async.commit_group;" ::: "memory");
}
__device__ __forceinline__ void ldm_x4(uint32_t* r, uint32_t addr) {
    asm volatile("ldmatrix.sync.aligned.m8n8.x4.shared.b16 {%0,%1,%2,%3}, [%4];"
                 : "=r"(r[0]), "=r"(r[1]), "=r"(r[2]), "=r"(r[3]) : "r"(addr));
}
__device__ __forceinline__ void mma16816(float* c, const uint32_t* a,
                                         uint32_t b0, uint32_t b1) {
    asm volatile(
        "mma.sync.aligned.m16n8k16.row.col.f32.bf16.bf16.f32 "
        "{%0,%1,%2,%3}, {%4,%5,%6,%7}, {%8,%9}, {%0,%1,%2,%3};"
        : "+f"(c[0]), "+f"(c[1]), "+f"(c[2]), "+f"(c[3])
        : "r"(a[0]), "r"(a[1]), "r"(a[2]), "r"(a[3]), "r"(b0), "r"(b1));
}

// ---------------------------------------------------------------------------
// Kernel 0: 2-way bf16 split (exact residual).
// ---------------------------------------------------------------------------
struct __align__(8) bf4 { __nv_bfloat16 v[4]; };

__global__ void split2(const float* __restrict__ in, __nv_bfloat16* __restrict__ o0,
                       __nv_bfloat16* __restrict__ o1, int n4)
{
    int i = blockIdx.x * blockDim.x + threadIdx.x;
    if (i >= n4) return;
    float4 f = ((const float4*)in)[i];
    bf4 a0, a1;
#pragma unroll
    for (int e = 0; e < 4; e++) {
        float v = (&f.x)[e];
        __nv_bfloat16 b0 = __float2bfloat16_rn(v);
        float r = v - __bfloat162float(b0);
        a0.v[e] = b0;
        a1.v[e] = __float2bfloat16_rn(r);
    }
    ((bf4*)o0)[i] = a0;
    ((bf4*)o1)[i] = a1;
}

// ---------------------------------------------------------------------------
// Kernel 1: h ~= x @ W_enc^T via warp-level bf16 mma.sync, 3-pass 2-way split.
// CTA tile 128x128, 128 threads (4 warps, each 64x64). Passes (1,0),(0,1),(0,0),
// all chained in-MMA. Accuracy target is only ~1e-4 (fix_h patches the rest).
// ---------------------------------------------------------------------------
#define NTILES  96       // 3 passes * 32 k64-tiles
#define SMEM_GEMM (4 * 16384)   // A0,B0,A1,B1

__global__ __launch_bounds__(128, 1)
void gemm_mma_bf16(float* __restrict__ C,
                   const __nv_bfloat16* __restrict__ A2,
                   const __nv_bfloat16* __restrict__ B2)
{
    extern __shared__ char sm[];
    const uint32_t sb = smem_u32(sm);
    const int tid = threadIdx.x;
    const int l = tid & 31;
    const int w = tid >> 5;
    const int warp_m = (w >> 1) * 64;
    const int warp_n = (w & 1) * 64;
    const int bm = blockIdx.y * 128;
    const int bn = blockIdx.x * 128;

    // pass -> (A split idx, B split idx): (1,0),(0,1),(0,0)
    const uint32_t AI_PK = 0x001u;
    const uint32_t BI_PK = 0x010u;

    float c[4][8][4];
#pragma unroll
    for (int mi = 0; mi < 4; mi++)
#pragma unroll
        for (int ni = 0; ni < 8; ni++)
#pragma unroll
            for (int q = 0; q < 4; q++) c[mi][ni][q] = 0.0f;

    // Per-lane ldmatrix row/chunk components (constant across tiles).
    const int arow = warp_m + (l & 15);                    // + 16*mi
    const int achb = (l >> 4);                             // + 2*kb
    const int brow = warp_n + (l & 7) + ((l >> 4) << 3);   // + 16*bi
    const int bchb = ((l >> 3) & 1);                       // + 2*kb

    auto load_tile = [&](int tl, int buf) {
        const int pass = tl >> 5;
        const int kt = tl & 31;
        const int ai = (AI_PK >> (4 * pass)) & 0xF;
        const int bi = (BI_PK >> (4 * pass)) & 0xF;
        const __nv_bfloat16* gA = A2 + (size_t)ai * (B_SZ * NIN)
                                     + (size_t)bm * NIN + kt * 64;
        const __nv_bfloat16* gB = B2 + (size_t)bi * (NOUT * NIN)
                                     + (size_t)bn * NIN + kt * 64;
        const uint32_t ab = sb + buf * 32768;
        const uint32_t bb = ab + 16384;
#pragma unroll
        for (int j = 0; j < 8; j++) {
            const int cid = j * 128 + tid;        // 0..1023
            const int row = cid >> 3, ch = cid & 7;
            const uint32_t sw = (uint32_t)row * 128 + (uint32_t)(ch ^ (row & 7)) * 16;
            cp16(ab + sw, gA + (size_t)row * NIN + ch * 8);
            cp16(bb + sw, gB + (size_t)row * NIN + ch * 8);
        }
        cp_commit();
    };

    auto ld_frags = [&](uint32_t ab, uint32_t bb, int kb,
                        uint32_t fa[4][4], uint32_t fb[4][4]) {
#pragma unroll
        for (int mi = 0; mi < 4; mi++) {
            const int row = arow + 16 * mi;
            const int ch = 2 * kb + achb;
            ldm_x4(fa[mi], ab + row * 128 + ((ch ^ (row & 7)) * 16));
        }
#pragma unroll
        for (int bi = 0; bi < 4; bi++) {
            const int row = brow + 16 * bi;
            const int ch = 2 * kb + bchb;
            ldm_x4(fb[bi], bb + row * 128 + ((ch ^ (row & 7)) * 16));
        }
    };

    uint32_t FA[2][4][4], FB[2][4][4];

    load_tile(0, 0);
    for (int tl = 0; tl < NTILES; tl++) {
        const int buf = tl & 1;
        if (tl + 1 < NTILES) {
            load_tile(tl + 1, buf ^ 1);
            asm volatile("cp.async.wait_group 1;" ::: "memory");
        } else {
            asm volatile("cp.async.wait_group 0;" ::: "memory");
        }
        __syncthreads();

        const uint32_t ab = sb + buf * 32768;
        const uint32_t bb = ab + 16384;

        ld_frags(ab, bb, 0, FA[0], FB[0]);
#pragma unroll
        for (int kb = 0; kb < 4; kb++) {
            if (kb < 3) ld_frags(ab, bb, kb + 1, FA[(kb + 1) & 1], FB[(kb + 1) & 1]);
            uint32_t (*fa)[4] = FA[kb & 1];
            uint32_t (*fb)[4] = FB[kb & 1];
#pragma unroll
            for (int mi = 0; mi < 4; mi++)
#pragma unroll
                for (int bi = 0; bi < 4; bi++) {
                    mma16816(c[mi][2 * bi],     fa[mi], fb[bi][0], fb[bi][1]);
                    mma16816(c[mi][2 * bi + 1], fa[mi], fb[bi][2], fb[bi][3]);
                }
        }
        __syncthreads();
    }

    // Epilogue: fragment layout -> global fp32.
#pragma unroll
    for (int mi = 0; mi < 4; mi++)
#pragma unroll
        for (int ni = 0; ni < 8; ni++) {
            const int row = bm + warp_m + 16 * mi + (l >> 2);
            const int col = bn + warp_n + 8 * ni + (l & 3) * 2;
            float2 v0; v0.x = c[mi][ni][0]; v0.y = c[mi][ni][1];
            float2 v1; v1.x = c[mi][ni][2]; v1.y = c[mi][ni][3];
            *(float2*)&C[(size_t)row * NOUT + col]       = v0;
            *(float2*)&C[(size_t)(row + 8) * NOUT + col] = v1;
        }
}

// ---------------------------------------------------------------------------
// Kernel 1b: threshold-risk detection + exact fp32 repair.
// One thread per neuron (b, j). Simulate the 10-step LIF trajectory with the
// approximate h; if any step's membrane is within RISK_DELTA of threshold,
// recompute h[b,j] as a strict k-ascending fp32 FMA chain (the exact
// arithmetic that measured rel_err 6.5e-8 in rounds 4-8) and overwrite.
// Non-risky neurons: |h_err|*1.25 << RISK_DELTA -> spike decisions provably
// identical to the exact-h computation.
// ---------------------------------------------------------------------------
__global__ __launch_bounds__(256)
void fix_h(float* __restrict__ h, const float* __restrict__ x,
           const float* __restrict__ W)
{
    const int idx = blockIdx.x * blockDim.x + threadIdx.x;
    const int b = idx >> 11;            // / NOUT
    const int j = idx & (NOUT - 1);

    const float hv = h[idx];
    float mem = 0.0f, spk = 0.0f;
    bool risky = false;
#pragma unroll
    for (int t = 0; t < TSTEPS; t++) {
        mem = mem * DECAY + hv - spk * TD;
        const float d = mem - THRESH;
        risky |= (fabsf(d) < RISK_DELTA);
        spk = (d > 0.0f) ? 1.0f : 0.0f;
    }
    if (!risky) return;

    // Exact sequential fp32 dot, k ascending, single accumulator.
    const float* xr = x + (size_t)b * NIN;
    const float* wr = W + (size_t)j * NIN;
    float acc = 0.0f;
    for (int k = 0; k < NIN; k += 4) {
        const float4 xv = *(const float4*)(xr + k);
        const float4 wv = *(const float4*)(wr + k);
        acc = fmaf(xv.x, wv.x, acc);
        acc = fmaf(xv.y, wv.y, acc);
        acc = fmaf(xv.z, wv.z, acc);
        acc = fmaf(xv.w, wv.w, acc);
    }
    h[idx] = acc;
}

// ---------------------------------------------------------------------------
// Kernel 2: SNN recurrence (R5 version — measured best). One CTA per row.
// ---------------------------------------------------------------------------
__global__ __launch_bounds__(256)
void snn_steps(const float* __restrict__ h, const float* __restrict__ Wdec,
               const float* __restrict__ yoh, float* __restrict__ out,
               float* __restrict__ lossPartial)
{
    __shared__ float red[8 * NC + NC];

    const int b = blockIdx.x;
    const int tid = threadIdx.x;
    const int warp = tid >> 5, lane = tid & 31;

    unsigned long long w2[8][5];
#pragma unroll
    for (int i = 0; i < 8; i++) {
        const int j = tid + 256 * i;
#pragma unroll
        for (int cc = 0; cc < 5; cc++)
            w2[i][cc] = pack2(Wdec[(2 * cc) * NOUT + j],
                              Wdec[(2 * cc + 1) * NOUT + j]);
    }

    float hreg[8], mem[8], spk[8];
#pragma unroll
    for (int i = 0; i < 8; i++) {
        hreg[i] = h[(size_t)b * NOUT + tid + 256 * i];
        mem[i] = 0.0f; spk[i] = 0.0f;
    }

    float ym = 0.0f, ys = 0.0f, yo = 0.0f, lossc = 0.0f;
    if (tid < NC) yo = yoh[b * NC + tid];
    __syncthreads();

    for (int t = 0; t < TSTEPS; t++) {
        unsigned long long acc2[5];
#pragma unroll
        for (int cc = 0; cc < 5; cc++) acc2[cc] = 0ull;

#pragma unroll
        for (int i = 0; i < 8; i++) {
            mem[i] = mem[i] * DECAY + hreg[i] - spk[i] * TD;
            spk[i] = (mem[i] > THRESH) ? 1.0f : 0.0f;
            const int j = tid + 256 * i;
            out[(size_t)t * (B_SZ * NOUT) + (size_t)b * NOUT + j] = spk[i];
            const unsigned long long s2 = pack2(spk[i], spk[i]);
#pragma unroll
            for (int cc = 0; cc < 5; cc++)
                acc2[cc] = ffma2(s2, w2[i][cc], acc2[cc]);
        }

#pragma unroll
        for (int cc = 0; cc < 5; cc++) {
#pragma unroll
            for (int o = 16; o > 0; o >>= 1) {
                unsigned long long other =
                    __shfl_down_sync(0xffffffffu, acc2[cc], o);
                acc2[cc] = fadd2(acc2[cc], other);
            }
        }
        if (lane == 0) {
#pragma unroll
            for (int cc = 0; cc < 5; cc++) {
                float lo, hi;
                unpack2(acc2[cc], lo, hi);
                red[warp * NC + 2 * cc]     = lo;
                red[warp * NC + 2 * cc + 1] = hi;
            }
        }
        __syncthreads();

        if (tid < NC) {
            float tot = 0.0f;
#pragma unroll
            for (int ww = 0; ww < 8; ww++) tot += red[ww * NC + tid];
            ym = ym * DECAY + tot - ys * TD;
            ys = (ym > THRESH) ? 1.0f : 0.0f;
            const float d = ys - yo;
            lossc = fmaf(d, d, lossc);
        }
        __syncthreads();
    }

    if (tid < NC) red[8 * NC + tid] = lossc;
    __syncthreads();
    if (tid == 0) {
        float s = 0.0f;
#pragma unroll
        for (int cc = 0; cc < NC; cc++) s += red[8 * NC + cc];
        lossPartial[b] = s;
    }
}

// ---------------------------------------------------------------------------
// Kernel 3: reduce per-row loss partials -> out[out_size-1]
// ---------------------------------------------------------------------------
__global__ void loss_reduce(const float* __restrict__ lp, float* __restrict__ out,
                            int out_size)
{
    __shared__ float s[256];
    float v = 0.0f;
    for (int i = threadIdx.x; i < B_SZ; i += 256) v += lp[i];
    s[threadIdx.x] = v;
    __syncthreads();
    for (int o = 128; o > 0; o >>= 1) {
        if (threadIdx.x < o) s[threadIdx.x] += s[threadIdx.x + o];
        __syncthreads();
    }
    if (threadIdx.x == 0)
        out[out_size - 1] = s[0] / (float)(B_SZ * NC);
}

// ---------------------------------------------------------------------------
extern "C" void kernel_launch(void* const* d_in, const int* in_sizes, int n_in,
                              void* d_out, int out_size)
{
    const float* x     = (const float*)d_in[0];   // [1024, 2048]
    const float* W_enc = (const float*)d_in[1];   // [2048, 2048]
    const float* W_dec = (const float*)d_in[2];   // [10, 2048]
    const float* y_oh  = (const float*)d_in[3];   // [1024, 10]
    float* out = (float*)d_out;

    float *h, *lp;
    cudaGetSymbolAddress((void**)&h, g_h);
    cudaGetSymbolAddress((void**)&lp, g_lossPartial);
    __nv_bfloat16 *a2, *b2;
    cudaGetSymbolAddress((void**)&a2, g_Asp);
    cudaGetSymbolAddress((void**)&b2, g_Bsp);

    // Split x and W_enc into 2 bf16 components each.
    const int nA = B_SZ * NIN, nB = NOUT * NIN;
    split2<<<(nA / 4 + 255) / 256, 256>>>(x, a2, a2 + nA, nA / 4);
    split2<<<(nB / 4 + 255) / 256, 256>>>(W_enc, b2, b2 + nB, nB / 4);

    // Approximate tensor-core GEMM (grid 16 x 8 = 128 CTAs).
    cudaFuncSetAttribute(gemm_mma_bf16, cudaFuncAttributeMaxDynamicSharedMemorySize,
                         SMEM_GEMM);
    gemm_mma_bf16<<<dim3(NOUT / 128, B_SZ / 128), 128, SMEM_GEMM>>>(h, a2, b2);

    // Detect threshold-risky neurons, repair their h exactly.
    fix_h<<<(B_SZ * NOUT) / 256, 256>>>(h, x, W_enc);

    // Recurrence + loss
    snn_steps<<<B_SZ, 256>>>(h, W_dec, y_oh, out, lp);
    loss_reduce<<<1, 256>>>(lp, out, out_size);
}

// round 13
// speedup vs baseline: 1.3220x; 1.1304x over previous
#include <cuda_runtime.h>
#include <cuda_bf16.h>
#include <cstdint>

// Problem constants (fixed by the dataset)
#define B_SZ   1024
#define NIN    2048
#define NOUT   2048
#define NC     10
#define TSTEPS 10

#define DECAY  0.2f
#define THRESH 0.5f
#define TD     0.1f   // THRESH * DECAY
#define RISK_DELTA 1e-3f

// Scratch
__device__ float g_h[B_SZ * NOUT];
__device__ float g_lossPartial[B_SZ];
__device__ int   g_riskList[B_SZ * NOUT];
__device__ int   g_riskCount;
// 2-way bf16 splits of x and W_enc (16B-aligned for cp.async)
__device__ __align__(16) __nv_bfloat16 g_Asp[2 * B_SZ * NIN];   // 8 MB
__device__ __align__(16) __nv_bfloat16 g_Bsp[2 * NOUT * NIN];   // 16 MB

// ---------------------------------------------------------------------------
// Packed fp32x2 helpers (for the snn kernel)
// ---------------------------------------------------------------------------
__device__ __forceinline__ unsigned long long pack2(float lo, float hi) {
    unsigned long long d;
    asm("mov.b64 %0, {%1, %2};" : "=l"(d)
        : "r"(__float_as_int(lo)), "r"(__float_as_int(hi)));
    return d;
}
__device__ __forceinline__ void unpack2(unsigned long long v, float& lo, float& hi) {
    int a, b;
    asm("mov.b64 {%0, %1}, %2;" : "=r"(a), "=r"(b) : "l"(v));
    lo = __int_as_float(a); hi = __int_as_float(b);
}
__device__ __forceinline__ unsigned long long ffma2(unsigned long long a,
                                                    unsigned long long b,
                                                    unsigned long long c) {
    unsigned long long d;
    asm("fma.rn.f32x2 %0, %1, %2, %3;" : "=l"(d) : "l"(a), "l"(b), "l"(c));
    return d;
}
__device__ __forceinline__ unsigned long long fadd2(unsigned long long a,
                                                    unsigned long long b) {
    unsigned long long d;
    asm("add.rn.f32x2 %0, %1, %2;" : "=l"(d) : "l"(a), "l"(b));
    return d;
}

// ---------------------------------------------------------------------------
// sm_80-era PTX helpers (valid on compute_103 base target)
// ---------------------------------------------------------------------------
__device__ __forceinline__ uint32_t smem_u32(const void* p) {
    uint32_t a;
    asm("{ .reg .u64 t; cvta.to.shared.u64 t, %1; cvt.u32.u64 %0, t; }"
        : "=r"(a) : "l"(p));
    return a;
}
__device__ __forceinline__ void cp16(uint32_t saddr, const void* gaddr) {
    asm volatile("cp.async.cg.shared.global [%0], [%1], 16;"
                 :: "r"(saddr), "l"(gaddr) : "memory");
}
__device__ __forceinline__ void cp_commit() {
    asm volatile("cp.async.commit_group;" ::: "memory");
}
__device__ __forceinline__ void ldm_x4(uint32_t* r, uint32_t addr) {
    asm volatile("ldmatrix.sync.aligned.m8n8.x4.shared.b16 {%0,%1,%2,%3}, [%4];"
                 : "=r"(r[0]), "=r"(r[1]), "=r"(r[2]), "=r"(r[3]) : "r"(addr));
}
__device__ __forceinline__ void mma16816(float* c, const uint32_t* a,
                                         uint32_t b0, uint32_t b1) {
    asm volatile(
        "mma.sync.aligned.m16n8k16.row.col.f32.bf16.bf16.f32 "
        "{%0,%1,%2,%3}, {%4,%5,%6,%7}, {%8,%9}, {%0,%1,%2,%3};"
        : "+f"(c[0]), "+f"(c[1]), "+f"(c[2]), "+f"(c[3])
        : "r"(a[0]), "r"(a[1]), "r"(a[2]), "r"(a[3]), "r"(b0), "r"(b1));
}

// ---------------------------------------------------------------------------
// Kernel Z: zero the risky counter (runs first; stream-ordered).
// ---------------------------------------------------------------------------
__global__ void zero_count(int* cnt) { *cnt = 0; }

// ---------------------------------------------------------------------------
// Kernel 0: 2-way bf16 split (exact residual).
// ---------------------------------------------------------------------------
struct __align__(8) bf4 { __nv_bfloat16 v[4]; };

__global__ void split2(const float* __restrict__ in, __nv_bfloat16* __restrict__ o0,
                       __nv_bfloat16* __restrict__ o1, int n4)
{
    int i = blockIdx.x * blockDim.x + threadIdx.x;
    if (i >= n4) return;
    float4 f = ((const float4*)in)[i];
    bf4 a0, a1;
#pragma unroll
    for (int e = 0; e < 4; e++) {
        float v = (&f.x)[e];
        __nv_bfloat16 b0 = __float2bfloat16_rn(v);
        float r = v - __bfloat162float(b0);
        a0.v[e] = b0;
        a1.v[e] = __float2bfloat16_rn(r);
    }
    ((bf4*)o0)[i] = a0;
    ((bf4*)o1)[i] = a1;
}

// ---------------------------------------------------------------------------
// Kernel 1: h ~= x @ W_enc^T via warp-level bf16 mma.sync, 3-pass 2-way split.
// CTA tile 128x128, 128 threads (4 warps, each 64x64). Passes (1,0),(0,1),(0,0),
// all chained in-MMA. Accuracy target is only ~1e-4 (repair patches the rest).
// ---------------------------------------------------------------------------
#define NTILES  96       // 3 passes * 32 k64-tiles
#define SMEM_GEMM (4 * 16384)   // A0,B0,A1,B1

__global__ __launch_bounds__(128, 1)
void gemm_mma_bf16(float* __restrict__ C,
                   const __nv_bfloat16* __restrict__ A2,
                   const __nv_bfloat16* __restrict__ B2)
{
    extern __shared__ char sm[];
    const uint32_t sb = smem_u32(sm);
    const int tid = threadIdx.x;
    const int l = tid & 31;
    const int w = tid >> 5;
    const int warp_m = (w >> 1) * 64;
    const int warp_n = (w & 1) * 64;
    const int bm = blockIdx.y * 128;
    const int bn = blockIdx.x * 128;

    // pass -> (A split idx, B split idx): (1,0),(0,1),(0,0)
    const uint32_t AI_PK = 0x001u;
    const uint32_t BI_PK = 0x010u;

    float c[4][8][4];
#pragma unroll
    for (int mi = 0; mi < 4; mi++)
#pragma unroll
        for (int ni = 0; ni < 8; ni++)
#pragma unroll
            for (int q = 0; q < 4; q++) c[mi][ni][q] = 0.0f;

    // Per-lane ldmatrix row/chunk components (constant across tiles).
    const int arow = warp_m + (l & 15);                    // + 16*mi
    const int achb = (l >> 4);                             // + 2*kb
    const int brow = warp_n + (l & 7) + ((l >> 4) << 3);   // + 16*bi
    const int bchb = ((l >> 3) & 1);                       // + 2*kb

    auto load_tile = [&](int tl, int buf) {
        const int pass = tl >> 5;
        const int kt = tl & 31;
        const int ai = (AI_PK >> (4 * pass)) & 0xF;
        const int bi = (BI_PK >> (4 * pass)) & 0xF;
        const __nv_bfloat16* gA = A2 + (size_t)ai * (B_SZ * NIN)
                                     + (size_t)bm * NIN + kt * 64;
        const __nv_bfloat16* gB = B2 + (size_t)bi * (NOUT * NIN)
                                     + (size_t)bn * NIN + kt * 64;
        const uint32_t ab = sb + buf * 32768;
        const uint32_t bb = ab + 16384;
#pragma unroll
        for (int j = 0; j < 8; j++) {
            const int cid = j * 128 + tid;        // 0..1023
            const int row = cid >> 3, ch = cid & 7;
            const uint32_t sw = (uint32_t)row * 128 + (uint32_t)(ch ^ (row & 7)) * 16;
            cp16(ab + sw, gA + (size_t)row * NIN + ch * 8);
            cp16(bb + sw, gB + (size_t)row * NIN + ch * 8);
        }
        cp_commit();
    };

    auto ld_frags = [&](uint32_t ab, uint32_t bb, int kb,
                        uint32_t fa[4][4], uint32_t fb[4][4]) {
#pragma unroll
        for (int mi = 0; mi < 4; mi++) {
            const int row = arow + 16 * mi;
            const int ch = 2 * kb + achb;
            ldm_x4(fa[mi], ab + row * 128 + ((ch ^ (row & 7)) * 16));
        }
#pragma unroll
        for (int bi = 0; bi < 4; bi++) {
            const int row = brow + 16 * bi;
            const int ch = 2 * kb + bchb;
            ldm_x4(fb[bi], bb + row * 128 + ((ch ^ (row & 7)) * 16));
        }
    };

    uint32_t FA[2][4][4], FB[2][4][4];

    load_tile(0, 0);
    for (int tl = 0; tl < NTILES; tl++) {
        const int buf = tl & 1;
        if (tl + 1 < NTILES) {
            load_tile(tl + 1, buf ^ 1);
            asm volatile("cp.async.wait_group 1;" ::: "memory");
        } else {
            asm volatile("cp.async.wait_group 0;" ::: "memory");
        }
        __syncthreads();

        const uint32_t ab = sb + buf * 32768;
        const uint32_t bb = ab + 16384;

        ld_frags(ab, bb, 0, FA[0], FB[0]);
#pragma unroll
        for (int kb = 0; kb < 4; kb++) {
            if (kb < 3) ld_frags(ab, bb, kb + 1, FA[(kb + 1) & 1], FB[(kb + 1) & 1]);
            uint32_t (*fa)[4] = FA[kb & 1];
            uint32_t (*fb)[4] = FB[kb & 1];
#pragma unroll
            for (int mi = 0; mi < 4; mi++)
#pragma unroll
                for (int bi = 0; bi < 4; bi++) {
                    mma16816(c[mi][2 * bi],     fa[mi], fb[bi][0], fb[bi][1]);
                    mma16816(c[mi][2 * bi + 1], fa[mi], fb[bi][2], fb[bi][3]);
                }
        }
        __syncthreads();
    }

    // Epilogue: fragment layout -> global fp32.
#pragma unroll
    for (int mi = 0; mi < 4; mi++)
#pragma unroll
        for (int ni = 0; ni < 8; ni++) {
            const int row = bm + warp_m + 16 * mi + (l >> 2);
            const int col = bn + warp_n + 8 * ni + (l & 3) * 2;
            float2 v0; v0.x = c[mi][ni][0]; v0.y = c[mi][ni][1];
            float2 v1; v1.x = c[mi][ni][2]; v1.y = c[mi][ni][3];
            *(float2*)&C[(size_t)row * NOUT + col]       = v0;
            *(float2*)&C[(size_t)(row + 8) * NOUT + col] = v1;
        }
}

// ---------------------------------------------------------------------------
// Kernel 1b-A: detect threshold-risky neurons, append to compact list
// (warp-aggregated atomics: 1 atomicAdd per warp).
// ---------------------------------------------------------------------------
__global__ __launch_bounds__(256)
void detect_risky(const float* __restrict__ h, int* __restrict__ list,
                  int* __restrict__ count)
{
    const int idx = blockIdx.x * blockDim.x + threadIdx.x;
    const int lane = threadIdx.x & 31;

    const float hv = h[idx];
    float mem = 0.0f, spk = 0.0f;
    bool risky = false;
#pragma unroll
    for (int t = 0; t < TSTEPS; t++) {
        mem = mem * DECAY + hv - spk * TD;
        const float d = mem - THRESH;
        risky |= (fabsf(d) < RISK_DELTA);
        spk = (d > 0.0f) ? 1.0f : 0.0f;
    }

    const unsigned mask = __ballot_sync(0xffffffffu, risky);
    if (mask == 0) return;
    const int leader = __ffs(mask) - 1;
    int base = 0;
    if (lane == leader) base = atomicAdd(count, __popc(mask));
    base = __shfl_sync(0xffffffffu, base, leader);
    if (risky)
        list[base + __popc(mask & ((1u << lane) - 1u))] = idx;
}

// ---------------------------------------------------------------------------
// Kernel 1b-B: repair risky neurons. Grid-strided over the compacted list;
// every lane handles a different neuron -> full warp utilization, chains
// overlap. Arithmetic identical to R12 repair (k-ascending fp32 fmaf,
// single accumulator) -> identical repaired values.
// ---------------------------------------------------------------------------
__global__ __launch_bounds__(256)
void repair_risky(float* __restrict__ h, const float* __restrict__ x,
                  const float* __restrict__ W, const int* __restrict__ list,
                  const int* __restrict__ count)
{
    const int n = *count;
    for (int i = blockIdx.x * blockDim.x + threadIdx.x; i < n;
         i += gridDim.x * blockDim.x) {
        const int idx = list[i];
        const int b = idx >> 11;            // / NOUT
        const int j = idx & (NOUT - 1);
        const float* xr = x + (size_t)b * NIN;
        const float* wr = W + (size_t)j * NIN;
        float acc = 0.0f;
        for (int k = 0; k < NIN; k += 4) {
            const float4 xv = *(const float4*)(xr + k);
            const float4 wv = *(const float4*)(wr + k);
            acc = fmaf(xv.x, wv.x, acc);
            acc = fmaf(xv.y, wv.y, acc);
            acc = fmaf(xv.z, wv.z, acc);
            acc = fmaf(xv.w, wv.w, acc);
        }
        h[idx] = acc;
    }
}

// ---------------------------------------------------------------------------
// Kernel 2: SNN recurrence (R5 version — measured best). One CTA per row.
// ---------------------------------------------------------------------------
__global__ __launch_bounds__(256)
void snn_steps(const float* __restrict__ h, const float* __restrict__ Wdec,
               const float* __restrict__ yoh, float* __restrict__ out,
               float* __restrict__ lossPartial)
{
    __shared__ float red[8 * NC + NC];

    const int b = blockIdx.x;
    const int tid = threadIdx.x;
    const int warp = tid >> 5, lane = tid & 31;

    unsigned long long w2[8][5];
#pragma unroll
    for (int i = 0; i < 8; i++) {
        const int j = tid + 256 * i;
#pragma unroll
        for (int cc = 0; cc < 5; cc++)
            w2[i][cc] = pack2(Wdec[(2 * cc) * NOUT + j],
                              Wdec[(2 * cc + 1) * NOUT + j]);
    }

    float hreg[8], mem[8], spk[8];
#pragma unroll
    for (int i = 0; i < 8; i++) {
        hreg[i] = h[(size_t)b * NOUT + tid + 256 * i];
        mem[i] = 0.0f; spk[i] = 0.0f;
    }

    float ym = 0.0f, ys = 0.0f, yo = 0.0f, lossc = 0.0f;
    if (tid < NC) yo = yoh[b * NC + tid];
    __syncthreads();

    for (int t = 0; t < TSTEPS; t++) {
        unsigned long long acc2[5];
#pragma unroll
        for (int cc = 0; cc < 5; cc++) acc2[cc] = 0ull;

#pragma unroll
        for (int i = 0; i < 8; i++) {
            mem[i] = mem[i] * DECAY + hreg[i] - spk[i] * TD;
            spk[i] = (mem[i] > THRESH) ? 1.0f : 0.0f;
            const int j = tid + 256 * i;
            out[(size_t)t * (B_SZ * NOUT) + (size_t)b * NOUT + j] = spk[i];
            const unsigned long long s2 = pack2(spk[i], spk[i]);
#pragma unroll
            for (int cc = 0; cc < 5; cc++)
                acc2[cc] = ffma2(s2, w2[i][cc], acc2[cc]);
        }

#pragma unroll
        for (int cc = 0; cc < 5; cc++) {
#pragma unroll
            for (int o = 16; o > 0; o >>= 1) {
                unsigned long long other =
                    __shfl_down_sync(0xffffffffu, acc2[cc], o);
                acc2[cc] = fadd2(acc2[cc], other);
            }
        }
        if (lane == 0) {
#pragma unroll
            for (int cc = 0; cc < 5; cc++) {
                float lo, hi;
                unpack2(acc2[cc], lo, hi);
                red[warp * NC + 2 * cc]     = lo;
                red[warp * NC + 2 * cc + 1] = hi;
            }
        }
        __syncthreads();

        if (tid < NC) {
            float tot = 0.0f;
#pragma unroll
            for (int ww = 0; ww < 8; ww++) tot += red[ww * NC + tid];
            ym = ym * DECAY + tot - ys * TD;
            ys = (ym > THRESH) ? 1.0f : 0.0f;
            const float d = ys - yo;
            lossc = fmaf(d, d, lossc);
        }
        __syncthreads();
    }

    if (tid < NC) red[8 * NC + tid] = lossc;
    __syncthreads();
    if (tid == 0) {
        float s = 0.0f;
#pragma unroll
        for (int cc = 0; cc < NC; cc++) s += red[8 * NC + cc];
        lossPartial[b] = s;
    }
}

// ---------------------------------------------------------------------------
// Kernel 3: reduce per-row loss partials -> out[out_size-1]
// ---------------------------------------------------------------------------
__global__ void loss_reduce(const float* __restrict__ lp, float* __restrict__ out,
                            int out_size)
{
    __shared__ float s[256];
    float v = 0.0f;
    for (int i = threadIdx.x; i < B_SZ; i += 256) v += lp[i];
    s[threadIdx.x] = v;
    __syncthreads();
    for (int o = 128; o > 0; o >>= 1) {
        if (threadIdx.x < o) s[threadIdx.x] += s[threadIdx.x + o];
        __syncthreads();
    }
    if (threadIdx.x == 0)
        out[out_size - 1] = s[0] / (float)(B_SZ * NC);
}

// ---------------------------------------------------------------------------
extern "C" void kernel_launch(void* const* d_in, const int* in_sizes, int n_in,
                              void* d_out, int out_size)
{
    const float* x     = (const float*)d_in[0];   // [1024, 2048]
    const float* W_enc = (const float*)d_in[1];   // [2048, 2048]
    const float* W_dec = (const float*)d_in[2];   // [10, 2048]
    const float* y_oh  = (const float*)d_in[3];   // [1024, 10]
    float* out = (float*)d_out;

    float *h, *lp;
    cudaGetSymbolAddress((void**)&h, g_h);
    cudaGetSymbolAddress((void**)&lp, g_lossPartial);
    __nv_bfloat16 *a2, *b2;
    cudaGetSymbolAddress((void**)&a2, g_Asp);
    cudaGetSymbolAddress((void**)&b2, g_Bsp);
    int *rl, *rc;
    cudaGetSymbolAddress((void**)&rl, g_riskList);
    cudaGetSymbolAddress((void**)&rc, g_riskCount);

    // Zero the risky counter (stream-ordered before detect).
    zero_count<<<1, 1>>>(rc);

    // Split x and W_enc into 2 bf16 components each.
    const int nA = B_SZ * NIN, nB = NOUT * NIN;
    split2<<<(nA / 4 + 255) / 256, 256>>>(x, a2, a2 + nA, nA / 4);
    split2<<<(nB / 4 + 255) / 256, 256>>>(W_enc, b2, b2 + nB, nB / 4);

    // Approximate tensor-core GEMM (grid 16 x 8 = 128 CTAs).
    cudaFuncSetAttribute(gemm_mma_bf16, cudaFuncAttributeMaxDynamicSharedMemorySize,
                         SMEM_GEMM);
    gemm_mma_bf16<<<dim3(NOUT / 128, B_SZ / 128), 128, SMEM_GEMM>>>(h, a2, b2);

    // Detect threshold-risky neurons (compact list), then repair exactly.
    detect_risky<<<(B_SZ * NOUT) / 256, 256>>>(h, rl, rc);
    repair_risky<<<296, 256>>>(h, x, W_enc, rl, rc);

    // Recurrence + loss
    snn_steps<<<B_SZ, 256>>>(h, W_dec, y_oh, out, lp);
    loss_reduce<<<1, 256>>>(lp, out, out_size);
}